// round 4
// baseline (speedup 1.0000x reference)
#include <cuda_runtime.h>
#include <cuda_bf16.h>
#include <math.h>

// Problem constants
#define B_   16
#define L_   256
#define LQ_  64
#define ET_  128
#define H_   4
#define ETK_ 32
#define DIM_ 64
#define D_IN_ 32
#define IE_  8

typedef unsigned long long ull;

// ---------------- scratch (device globals; no allocation) ----------------
__device__ float g_q[H_ * LQ_ * ETK_];          // (h, q, e)  pre-scaled by 1/sqrt(32)
__device__ float g_k[B_ * H_ * L_ * ETK_];      // (b, h, l, e)
__device__ float g_att[B_ * LQ_ * ET_];         // (b, q, h*32+d)  compact (ones folded)
__device__ float g_Wc[ET_ * ET_];               // 128 x 128 : compact rows of Wo @ W_ih
__device__ float g_bc[ET_];                     // combined bias (incl. ones-rows fold)
__device__ float g_pre[B_ * LQ_ * ET_];         // (b, t, j)

// ======================================================================
// Kernel 1 (fused): time-embed + Q/K projections  AND  Wc/bc combine.
// ======================================================================
__global__ void stage1_kernel(
    const float* __restrict__ times, const float* __restrict__ query,
    const float* __restrict__ w_lin, const float* __restrict__ b_lin,
    const float* __restrict__ w_per, const float* __restrict__ b_per,
    const float* __restrict__ Wk, const float* __restrict__ bk,
    const float* __restrict__ Wq, const float* __restrict__ bq,
    const float* __restrict__ Wo, const float* __restrict__ bo,
    const float* __restrict__ W_ih, const float* __restrict__ b_ih,
    const float* __restrict__ b_hh)
{
    extern __shared__ float sm[];
    float* s_a = sm;              // 16 x 128
    float* s_w = sm + 16 * 128;   // 128 x 128
    __shared__ float tv[16];

    const int tid = threadIdx.x;
    const int bx  = blockIdx.x;
    const int tx = tid & 31;
    const int ty = tid >> 5;

    if (bx < 260) {
        const bool is_q = (bx >= 256);
        const int r0 = bx * 16;
        if (tid < 16) tv[tid] = is_q ? query[r0 - 4096 + tid] : times[r0 + tid];
        __syncthreads();

        const float wl = w_lin[0], bl = b_lin[0];
        for (int idx = tid; idx < 16 * 128; idx += 256) {
            int r = idx >> 7, c = idx & 127;
            float t = tv[r];
            s_a[idx] = (c == 0) ? fmaf(t, wl, bl)
                                : __sinf(fmaf(t, w_per[c - 1], b_per[c - 1]));
        }
        const float* W    = is_q ? Wq : Wk;
        const float* bias = is_q ? bq : bk;
#pragma unroll
        for (int idx = tid * 4; idx < 128 * 128; idx += 1024)
            *(float4*)(s_w + idx) = *(const float4*)(W + idx);
        __syncthreads();

        float acc[2][4];
#pragma unroll
        for (int r = 0; r < 2; r++)
#pragma unroll
            for (int c = 0; c < 4; c++) acc[r][c] = 0.f;

#pragma unroll 4
        for (int i = 0; i < 128; i++) {
            float4 w = *(const float4*)(s_w + i * 128 + 4 * tx);
            float e0 = s_a[(2 * ty) * 128 + i];
            float e1 = s_a[(2 * ty + 1) * 128 + i];
            acc[0][0] = fmaf(e0, w.x, acc[0][0]); acc[0][1] = fmaf(e0, w.y, acc[0][1]);
            acc[0][2] = fmaf(e0, w.z, acc[0][2]); acc[0][3] = fmaf(e0, w.w, acc[0][3]);
            acc[1][0] = fmaf(e1, w.x, acc[1][0]); acc[1][1] = fmaf(e1, w.y, acc[1][1]);
            acc[1][2] = fmaf(e1, w.z, acc[1][2]); acc[1][3] = fmaf(e1, w.w, acc[1][3]);
        }

        const float scale = is_q ? 0.17677669529663687f : 1.0f;
#pragma unroll
        for (int r = 0; r < 2; r++) {
            int grow = r0 + 2 * ty + r;
#pragma unroll
            for (int c = 0; c < 4; c++) {
                int col = 4 * tx + c;
                float v = (acc[r][c] + bias[col]) * scale;
                int h = col >> 5, e = col & 31;
                if (is_q) g_q[(h * LQ_ + (grow - 4096)) * ETK_ + e] = v;
                else {
                    int b = grow >> 8, l = grow & 255;
                    g_k[((b * H_ + h) * L_ + l) * ETK_ + e] = v;
                }
            }
        }
    } else if (bx < 268) {
        const int cr0 = (bx - 260) * 16;
        for (int idx = tid; idx < 16 * 128; idx += 256) {
            int rr = idx >> 7, c = idx & 127;
            int cr = cr0 + rr;
            int r = (cr >> 5) * 64 + (cr & 31);
            s_a[idx] = Wo[r * 128 + c];
        }
#pragma unroll
        for (int idx = tid * 4; idx < 128 * 128; idx += 1024)
            *(float4*)(s_w + idx) = *(const float4*)(W_ih + idx);
        __syncthreads();

        float acc[2][4];
#pragma unroll
        for (int r = 0; r < 2; r++)
#pragma unroll
            for (int c = 0; c < 4; c++) acc[r][c] = 0.f;

#pragma unroll 4
        for (int i = 0; i < 128; i++) {
            float4 w = *(const float4*)(s_w + i * 128 + 4 * tx);
            float e0 = s_a[(2 * ty) * 128 + i];
            float e1 = s_a[(2 * ty + 1) * 128 + i];
            acc[0][0] = fmaf(e0, w.x, acc[0][0]); acc[0][1] = fmaf(e0, w.y, acc[0][1]);
            acc[0][2] = fmaf(e0, w.z, acc[0][2]); acc[0][3] = fmaf(e0, w.w, acc[0][3]);
            acc[1][0] = fmaf(e1, w.x, acc[1][0]); acc[1][1] = fmaf(e1, w.y, acc[1][1]);
            acc[1][2] = fmaf(e1, w.z, acc[1][2]); acc[1][3] = fmaf(e1, w.w, acc[1][3]);
        }
#pragma unroll
        for (int r = 0; r < 2; r++)
#pragma unroll
            for (int c = 0; c < 4; c++)
                g_Wc[(cr0 + 2 * ty + r) * 128 + 4 * tx + c] = acc[r][c];
    } else {
        const int j = tid & 127, hf = tid >> 7;
        float accv = 0.f;
#pragma unroll 4
        for (int i = 0; i < 64; i++) {
            int oi = hf * 64 + i;
            int r = (oi >> 5) * 64 + 32 + (oi & 31);
            accv += Wo[r * 128 + j];
        }
        s_a[hf * 128 + j] = accv;
        __syncthreads();
        float v = 0.f;
        if (tid < 128) v = bo[tid] + s_a[tid] + s_a[128 + tid];
        __syncthreads();
        if (tid < 128) s_a[tid] = v;
#pragma unroll
        for (int idx = tid * 4; idx < 128 * 128; idx += 1024)
            *(float4*)(s_w + idx) = *(const float4*)(W_ih + idx);
        __syncthreads();
        if (tid < 128) {
            float acc = b_ih[tid] + b_hh[tid];
#pragma unroll 8
            for (int i = 0; i < 128; i++)
                acc = fmaf(s_a[i], s_w[i * 128 + tid], acc);
            g_bc[tid] = acc;
        }
    }
}

// ======================================================================
// Kernel 2: masked per-feature attention (compact output).
// ======================================================================
__global__ void attn_kernel(const float* __restrict__ x,
                            const float* __restrict__ mask)
{
    extern __shared__ float smem[];
    float*  qv  = smem;
    float*  s_s = smem + 512;
    float2* mxm = (float2*)(smem + 512 + 4096);

    const int tid = threadIdx.x;
    const int qt = blockIdx.x, h = blockIdx.y, b = blockIdx.z;

    qv[tid] = g_q[(h * LQ_ + qt * 16) * ETK_ + tid];

    const float* xb = x    + b * L_ * D_IN_;
    const float* mb = mask + b * L_ * D_IN_;
    for (int idx = tid; idx < L_ * D_IN_; idx += 512) {
        float m = mb[idx];
        mxm[idx] = make_float2(m * xb[idx], m);
    }
    __syncthreads();

    {
        const int k  = tid & 255;
        const int qh = tid >> 8;
        const float* kp = g_k + ((b * H_ + h) * L_ + k) * ETK_;
        float kv[32];
#pragma unroll
        for (int i = 0; i < 8; i++) {
            float4 v = *(const float4*)(kp + 4 * i);
            kv[4 * i] = v.x; kv[4 * i + 1] = v.y; kv[4 * i + 2] = v.z; kv[4 * i + 3] = v.w;
        }
#pragma unroll
        for (int qq = 0; qq < 8; qq++) {
            int q = qh * 8 + qq;
            float acc = 0.f;
#pragma unroll
            for (int e = 0; e < 32; e++) acc = fmaf(qv[q * 32 + e], kv[e], acc);
            s_s[q * 256 + k] = acc;
        }
    }
    __syncthreads();

    {
        const int wq = tid >> 5, lane = tid & 31;
        float vals[8], m = -1e30f;
#pragma unroll
        for (int i = 0; i < 8; i++) {
            vals[i] = s_s[wq * 256 + lane + 32 * i];
            m = fmaxf(m, vals[i]);
        }
#pragma unroll
        for (int off = 16; off; off >>= 1)
            m = fmaxf(m, __shfl_xor_sync(0xffffffffu, m, off));
#pragma unroll
        for (int i = 0; i < 8; i++)
            s_s[wq * 256 + lane + 32 * i] = __expf(vals[i] - m);
    }
    __syncthreads();

    {
        const int q = tid >> 5, d = tid & 31;
        float num = 0.f, den = 0.f;
        const float* ep = s_s + q * 256;
        const float2* vp = mxm + d;
#pragma unroll 4
        for (int k = 0; k < 256; k++) {
            float  e = ep[k];
            float2 v = vp[k * 32];
            num = fmaf(e, v.x, num);
            den = fmaf(e, v.y, den);
        }
        float att = (den > 0.f) ? (num / den) : 0.f;
        g_att[(b * LQ_ + qt * 16 + q) * ET_ + h * ETK_ + d] = att;
    }
}

// ======================================================================
// Kernel 3: pre = att_c @ Wc + bc   (1024 x 128, K=128)
// ======================================================================
__global__ void pre_kernel()
{
    __shared__ float a_s[16 * 128];
    __shared__ float w_s[128 * 32];

    const int tid = threadIdx.x;
    const int cc = blockIdx.x;
    const int r0 = blockIdx.y * 16;

#pragma unroll
    for (int idx = tid * 4; idx < 16 * 128; idx += 1024)
        *(float4*)(a_s + idx) = *(const float4*)(g_att + r0 * 128 + idx);

#pragma unroll
    for (int f = tid * 4; f < 128 * 32; f += 1024) {
        int i = f >> 5, c = f & 31;
        *(float4*)(w_s + f) = *(const float4*)(g_Wc + i * 128 + cc * 32 + c);
    }
    __syncthreads();

    const int tx = tid & 31;
    const int ty = tid >> 5;

    float a0 = 0.f, a1 = 0.f;
#pragma unroll 8
    for (int i = 0; i < 128; i++) {
        float w = w_s[i * 32 + tx];
        a0 = fmaf(a_s[(2 * ty) * 128 + i],     w, a0);
        a1 = fmaf(a_s[(2 * ty + 1) * 128 + i], w, a1);
    }

    const int col = cc * 32 + tx;
    const float bias = g_bc[col];
    g_pre[(r0 + 2 * ty) * 128 + col]     = a0 + bias;
    g_pre[(r0 + 2 * ty + 1) * 128 + col] = a1 + bias;
}

// ======================================================================
// Kernel 4: RNN + regressor. grid 16 x 256 threads.
//  - lane pair (2k,2k+1) of warp w handles column j = w*16+k; each lane
//    computes one 64-length half of the dot with packed f32x2 FMAs,
//    combined with one shfl_xor. Double-buffered h => ONE barrier/step.
// ======================================================================
__device__ __forceinline__ float fast_tanh(float z)
{
    float e2 = __expf(2.f * z);
    return 1.f - __fdividef(2.f, e2 + 1.f);
}

__device__ __forceinline__ void ffma2(ull& acc, ull a, ull b)
{
    asm("fma.rn.f32x2 %0, %1, %2, %0;" : "+l"(acc) : "l"(a), "l"(b));
}
__device__ __forceinline__ ull fadd2(ull a, ull b)
{
    ull r; asm("add.rn.f32x2 %0, %1, %2;" : "=l"(r) : "l"(a), "l"(b)); return r;
}
__device__ __forceinline__ float2 unpack2(ull a)
{
    float2 v; asm("mov.b64 {%0,%1}, %2;" : "=f"(v.x), "=f"(v.y) : "l"(a)); return v;
}

__device__ __forceinline__ void matvec128_2(const float* in_s, float* out_s,
                                            const float* __restrict__ Wg,
                                            const float* __restrict__ bg,
                                            int s, int j, int tid,
                                            float part[2][128])
{
    float a0 = 0.f, a1 = 0.f, a2 = 0.f, a3 = 0.f;
    const float* wp = Wg + (64 * s) * 128 + j;
#pragma unroll
    for (int i = 0; i < 64; i += 4) {
        a0 = fmaf(in_s[64 * s + i],     wp[i * 128],       a0);
        a1 = fmaf(in_s[64 * s + i + 1], wp[(i + 1) * 128], a1);
        a2 = fmaf(in_s[64 * s + i + 2], wp[(i + 2) * 128], a2);
        a3 = fmaf(in_s[64 * s + i + 3], wp[(i + 3) * 128], a3);
    }
    part[s][j] = (a0 + a1) + (a2 + a3);
    __syncthreads();
    if (tid < 128) out_s[tid] = bg[tid] + part[0][tid] + part[1][tid];
    __syncthreads();
}

__global__ void __launch_bounds__(256, 1)
rnn_regr_kernel(const float* __restrict__ W_hh,
                const float* __restrict__ r1_w, const float* __restrict__ r1_b,
                const float* __restrict__ r2_w, const float* __restrict__ r2_b,
                const float* __restrict__ r3_w, const float* __restrict__ r3_b,
                const float* __restrict__ r4_w, const float* __restrict__ r4_b,
                float* __restrict__ out)
{
    __shared__ float h2[2][128];
    __shared__ float v_s[128];
    __shared__ float part[2][128];

    const int tid  = threadIdx.x;
    const int w    = tid >> 5;
    const int l    = tid & 31;
    const int j    = w * 16 + (l >> 1);   // output column 0..127
    const int half = l & 1;               // which 64-row half of the dot
    const int i0   = half * 64;

    // Preload W_hh half-column into packed f32x2 registers
    ull wreg[32];
#pragma unroll
    for (int k = 0; k < 32; k++) {
        union { float2 f; ull u; } p;
        p.f.x = W_hh[(i0 + 2 * k) * 128 + j];
        p.f.y = W_hh[(i0 + 2 * k + 1) * 128 + j];
        wreg[k] = p.u;
    }

    const float* pre_b = g_pre + blockIdx.x * LQ_ * ET_;

    // step 0: h = tanh(pre[0]) (h_prev = 0)
    float h0 = fast_tanh(pre_b[j]);
    if (half == 0) h2[0][j] = h0;
    float pre_cur = pre_b[128 + j];
    __syncthreads();

    int cb = 0;
    for (int step = 1; step < LQ_; step++) {
        float pre_nxt = (step + 1 < LQ_) ? pre_b[(step + 1) * 128 + j] : 0.f;

        const ull* hp = (const ull*)(h2[cb] + i0);
        ull a0 = 0, a1 = 0, a2 = 0, a3 = 0;
#pragma unroll
        for (int k = 0; k < 32; k += 4) {
            ffma2(a0, hp[k],     wreg[k]);
            ffma2(a1, hp[k + 1], wreg[k + 1]);
            ffma2(a2, hp[k + 2], wreg[k + 2]);
            ffma2(a3, hp[k + 3], wreg[k + 3]);
        }
        ull s01 = fadd2(fadd2(a0, a1), fadd2(a2, a3));
        float2 sv = unpack2(s01);
        float s = sv.x + sv.y;
        s += __shfl_xor_sync(0xffffffffu, s, 1);

        float hn = fast_tanh(pre_cur + s);
        if (half == 0) h2[cb ^ 1][j] = hn;
        cb ^= 1;
        pre_cur = pre_nxt;
        __syncthreads();
    }

    // final hidden state lives in h2[cb]
    const int jj = tid & 127;
    const int ss = tid >> 7;
    matvec128_2(h2[cb], v_s,    r1_w, r1_b, ss, jj, tid, part);
    matvec128_2(v_s,    h2[cb], r2_w, r2_b, ss, jj, tid, part);
    matvec128_2(h2[cb], v_s,    r3_w, r3_b, ss, jj, tid, part);

    {
        int o = tid >> 5, lane = tid & 31;
        float acc = 0.f;
#pragma unroll
        for (int ii = 0; ii < 4; ii++) {
            int i = lane * 4 + ii;
            acc = fmaf(v_s[i], r4_w[i * 8 + o], acc);
        }
#pragma unroll
        for (int off = 16; off; off >>= 1)
            acc += __shfl_xor_sync(0xffffffffu, acc, off);
        if (lane == 0) out[blockIdx.x * 8 + o] = acc + r4_b[o];
    }
}

// ======================================================================
extern "C" void kernel_launch(void* const* d_in, const int* in_sizes, int n_in,
                              void* d_out, int out_size)
{
    const float* x     = (const float*)d_in[0];
    const float* times = (const float*)d_in[1];
    const float* mask  = (const float*)d_in[2];
    const float* query = (const float*)d_in[3];
    const float* w_lin = (const float*)d_in[4];
    const float* b_lin = (const float*)d_in[5];
    const float* w_per = (const float*)d_in[6];
    const float* b_per = (const float*)d_in[7];
    const float* Wq    = (const float*)d_in[8];
    const float* bq    = (const float*)d_in[9];
    const float* Wk    = (const float*)d_in[10];
    const float* bk    = (const float*)d_in[11];
    const float* Wo    = (const float*)d_in[12];
    const float* bo    = (const float*)d_in[13];
    const float* W_ih  = (const float*)d_in[14];
    const float* b_ih  = (const float*)d_in[15];
    const float* W_hh  = (const float*)d_in[16];
    const float* b_hh  = (const float*)d_in[17];
    const float* r1_w  = (const float*)d_in[18];
    const float* r1_b  = (const float*)d_in[19];
    const float* r2_w  = (const float*)d_in[20];
    const float* r2_b  = (const float*)d_in[21];
    const float* r3_w  = (const float*)d_in[22];
    const float* r3_b  = (const float*)d_in[23];
    const float* r4_w  = (const float*)d_in[24];
    const float* r4_b  = (const float*)d_in[25];
    float* out = (float*)d_out;

    const int S1_SMEM = (16 * 128 + 128 * 128) * 4;  // 73728
    cudaFuncSetAttribute(stage1_kernel,
                         cudaFuncAttributeMaxDynamicSharedMemorySize, S1_SMEM);
    stage1_kernel<<<269, 256, S1_SMEM>>>(times, query, w_lin, b_lin, w_per, b_per,
                                         Wk, bk, Wq, bq, Wo, bo, W_ih, b_ih, b_hh);

    const int ATTN_SMEM = (512 + 4096) * 4 + 256 * 32 * 8;  // 83968
    cudaFuncSetAttribute(attn_kernel,
                         cudaFuncAttributeMaxDynamicSharedMemorySize, ATTN_SMEM);
    attn_kernel<<<dim3(4, 4, 16), 512, ATTN_SMEM>>>(x, mask);

    pre_kernel<<<dim3(4, 64), 256>>>();

    rnn_regr_kernel<<<16, 256>>>(W_hh, r1_w, r1_b, r2_w, r2_b,
                                 r3_w, r3_b, r4_w, r4_b, out);
}

// round 5
// speedup vs baseline: 1.0024x; 1.0024x over previous
#include <cuda_runtime.h>
#include <cuda_bf16.h>
#include <math.h>

// Problem constants
#define B_   16
#define L_   256
#define LQ_  64
#define ET_  128
#define H_   4
#define ETK_ 32
#define DIM_ 64
#define D_IN_ 32
#define IE_  8

typedef unsigned long long ull;

// ---------------- scratch (device globals; no allocation) ----------------
__device__ float g_q[H_ * LQ_ * ETK_];          // (h, q, e)  pre-scaled by 1/sqrt(32)
__device__ float g_k[B_ * H_ * L_ * ETK_];      // (b, h, l, e)
__device__ float g_att[B_ * LQ_ * ET_];         // (b, q, h*32+d)  compact (ones folded)
__device__ float g_Wc[ET_ * ET_];               // 128 x 128 : compact rows of Wo @ W_ih
__device__ float g_bc[ET_];                     // combined bias (incl. ones-rows fold)
__device__ float g_pre[B_ * LQ_ * ET_];         // (b, t, j)

// ======================================================================
// Kernel 1 (fused): time-embed + Q/K projections  AND  Wc/bc combine.
// ======================================================================
__global__ void stage1_kernel(
    const float* __restrict__ times, const float* __restrict__ query,
    const float* __restrict__ w_lin, const float* __restrict__ b_lin,
    const float* __restrict__ w_per, const float* __restrict__ b_per,
    const float* __restrict__ Wk, const float* __restrict__ bk,
    const float* __restrict__ Wq, const float* __restrict__ bq,
    const float* __restrict__ Wo, const float* __restrict__ bo,
    const float* __restrict__ W_ih, const float* __restrict__ b_ih,
    const float* __restrict__ b_hh)
{
    extern __shared__ float sm[];
    float* s_a = sm;              // 16 x 128
    float* s_w = sm + 16 * 128;   // 128 x 128
    __shared__ float tv[16];

    const int tid = threadIdx.x;
    const int bx  = blockIdx.x;
    const int tx = tid & 31;
    const int ty = tid >> 5;

    if (bx < 260) {
        const bool is_q = (bx >= 256);
        const int r0 = bx * 16;
        if (tid < 16) tv[tid] = is_q ? query[r0 - 4096 + tid] : times[r0 + tid];
        __syncthreads();

        const float wl = w_lin[0], bl = b_lin[0];
        for (int idx = tid; idx < 16 * 128; idx += 256) {
            int r = idx >> 7, c = idx & 127;
            float t = tv[r];
            s_a[idx] = (c == 0) ? fmaf(t, wl, bl)
                                : __sinf(fmaf(t, w_per[c - 1], b_per[c - 1]));
        }
        const float* W    = is_q ? Wq : Wk;
        const float* bias = is_q ? bq : bk;
#pragma unroll
        for (int idx = tid * 4; idx < 128 * 128; idx += 1024)
            *(float4*)(s_w + idx) = *(const float4*)(W + idx);
        __syncthreads();

        float acc[2][4];
#pragma unroll
        for (int r = 0; r < 2; r++)
#pragma unroll
            for (int c = 0; c < 4; c++) acc[r][c] = 0.f;

#pragma unroll 4
        for (int i = 0; i < 128; i++) {
            float4 w = *(const float4*)(s_w + i * 128 + 4 * tx);
            float e0 = s_a[(2 * ty) * 128 + i];
            float e1 = s_a[(2 * ty + 1) * 128 + i];
            acc[0][0] = fmaf(e0, w.x, acc[0][0]); acc[0][1] = fmaf(e0, w.y, acc[0][1]);
            acc[0][2] = fmaf(e0, w.z, acc[0][2]); acc[0][3] = fmaf(e0, w.w, acc[0][3]);
            acc[1][0] = fmaf(e1, w.x, acc[1][0]); acc[1][1] = fmaf(e1, w.y, acc[1][1]);
            acc[1][2] = fmaf(e1, w.z, acc[1][2]); acc[1][3] = fmaf(e1, w.w, acc[1][3]);
        }

        const float scale = is_q ? 0.17677669529663687f : 1.0f;
#pragma unroll
        for (int r = 0; r < 2; r++) {
            int grow = r0 + 2 * ty + r;
#pragma unroll
            for (int c = 0; c < 4; c++) {
                int col = 4 * tx + c;
                float v = (acc[r][c] + bias[col]) * scale;
                int h = col >> 5, e = col & 31;
                if (is_q) g_q[(h * LQ_ + (grow - 4096)) * ETK_ + e] = v;
                else {
                    int b = grow >> 8, l = grow & 255;
                    g_k[((b * H_ + h) * L_ + l) * ETK_ + e] = v;
                }
            }
        }
    } else if (bx < 268) {
        const int cr0 = (bx - 260) * 16;
        for (int idx = tid; idx < 16 * 128; idx += 256) {
            int rr = idx >> 7, c = idx & 127;
            int cr = cr0 + rr;
            int r = (cr >> 5) * 64 + (cr & 31);
            s_a[idx] = Wo[r * 128 + c];
        }
#pragma unroll
        for (int idx = tid * 4; idx < 128 * 128; idx += 1024)
            *(float4*)(s_w + idx) = *(const float4*)(W_ih + idx);
        __syncthreads();

        float acc[2][4];
#pragma unroll
        for (int r = 0; r < 2; r++)
#pragma unroll
            for (int c = 0; c < 4; c++) acc[r][c] = 0.f;

#pragma unroll 4
        for (int i = 0; i < 128; i++) {
            float4 w = *(const float4*)(s_w + i * 128 + 4 * tx);
            float e0 = s_a[(2 * ty) * 128 + i];
            float e1 = s_a[(2 * ty + 1) * 128 + i];
            acc[0][0] = fmaf(e0, w.x, acc[0][0]); acc[0][1] = fmaf(e0, w.y, acc[0][1]);
            acc[0][2] = fmaf(e0, w.z, acc[0][2]); acc[0][3] = fmaf(e0, w.w, acc[0][3]);
            acc[1][0] = fmaf(e1, w.x, acc[1][0]); acc[1][1] = fmaf(e1, w.y, acc[1][1]);
            acc[1][2] = fmaf(e1, w.z, acc[1][2]); acc[1][3] = fmaf(e1, w.w, acc[1][3]);
        }
#pragma unroll
        for (int r = 0; r < 2; r++)
#pragma unroll
            for (int c = 0; c < 4; c++)
                g_Wc[(cr0 + 2 * ty + r) * 128 + 4 * tx + c] = acc[r][c];
    } else {
        const int j = tid & 127, hf = tid >> 7;
        float accv = 0.f;
#pragma unroll 4
        for (int i = 0; i < 64; i++) {
            int oi = hf * 64 + i;
            int r = (oi >> 5) * 64 + 32 + (oi & 31);
            accv += Wo[r * 128 + j];
        }
        s_a[hf * 128 + j] = accv;
        __syncthreads();
        float v = 0.f;
        if (tid < 128) v = bo[tid] + s_a[tid] + s_a[128 + tid];
        __syncthreads();
        if (tid < 128) s_a[tid] = v;
#pragma unroll
        for (int idx = tid * 4; idx < 128 * 128; idx += 1024)
            *(float4*)(s_w + idx) = *(const float4*)(W_ih + idx);
        __syncthreads();
        if (tid < 128) {
            float acc = b_ih[tid] + b_hh[tid];
#pragma unroll 8
            for (int i = 0; i < 128; i++)
                acc = fmaf(s_a[i], s_w[i * 128 + tid], acc);
            g_bc[tid] = acc;
        }
    }
}

// ======================================================================
// Kernel 2: masked per-feature attention (compact output).
// ======================================================================
__global__ void attn_kernel(const float* __restrict__ x,
                            const float* __restrict__ mask)
{
    extern __shared__ float smem[];
    float*  qv  = smem;
    float*  s_s = smem + 512;
    float2* mxm = (float2*)(smem + 512 + 4096);

    const int tid = threadIdx.x;
    const int qt = blockIdx.x, h = blockIdx.y, b = blockIdx.z;

    qv[tid] = g_q[(h * LQ_ + qt * 16) * ETK_ + tid];

    const float* xb = x    + b * L_ * D_IN_;
    const float* mb = mask + b * L_ * D_IN_;
    for (int idx = tid; idx < L_ * D_IN_; idx += 512) {
        float m = mb[idx];
        mxm[idx] = make_float2(m * xb[idx], m);
    }
    __syncthreads();

    {
        const int k  = tid & 255;
        const int qh = tid >> 8;
        const float* kp = g_k + ((b * H_ + h) * L_ + k) * ETK_;
        float kv[32];
#pragma unroll
        for (int i = 0; i < 8; i++) {
            float4 v = *(const float4*)(kp + 4 * i);
            kv[4 * i] = v.x; kv[4 * i + 1] = v.y; kv[4 * i + 2] = v.z; kv[4 * i + 3] = v.w;
        }
#pragma unroll
        for (int qq = 0; qq < 8; qq++) {
            int q = qh * 8 + qq;
            float acc = 0.f;
#pragma unroll
            for (int e = 0; e < 32; e++) acc = fmaf(qv[q * 32 + e], kv[e], acc);
            s_s[q * 256 + k] = acc;
        }
    }
    __syncthreads();

    {
        const int wq = tid >> 5, lane = tid & 31;
        float vals[8], m = -1e30f;
#pragma unroll
        for (int i = 0; i < 8; i++) {
            vals[i] = s_s[wq * 256 + lane + 32 * i];
            m = fmaxf(m, vals[i]);
        }
#pragma unroll
        for (int off = 16; off; off >>= 1)
            m = fmaxf(m, __shfl_xor_sync(0xffffffffu, m, off));
#pragma unroll
        for (int i = 0; i < 8; i++)
            s_s[wq * 256 + lane + 32 * i] = __expf(vals[i] - m);
    }
    __syncthreads();

    {
        const int q = tid >> 5, d = tid & 31;
        float num = 0.f, den = 0.f;
        const float* ep = s_s + q * 256;
        const float2* vp = mxm + d;
#pragma unroll 4
        for (int k = 0; k < 256; k++) {
            float  e = ep[k];
            float2 v = vp[k * 32];
            num = fmaf(e, v.x, num);
            den = fmaf(e, v.y, den);
        }
        float att = (den > 0.f) ? (num / den) : 0.f;
        g_att[(b * LQ_ + qt * 16 + q) * ET_ + h * ETK_ + d] = att;
    }
}

// ======================================================================
// Kernel 3: pre = att_c @ Wc + bc   (1024 x 128, K=128)
// ======================================================================
__global__ void pre_kernel()
{
    __shared__ float a_s[16 * 128];
    __shared__ float w_s[128 * 32];

    const int tid = threadIdx.x;
    const int cc = blockIdx.x;
    const int r0 = blockIdx.y * 16;

#pragma unroll
    for (int idx = tid * 4; idx < 16 * 128; idx += 1024)
        *(float4*)(a_s + idx) = *(const float4*)(g_att + r0 * 128 + idx);

#pragma unroll
    for (int f = tid * 4; f < 128 * 32; f += 1024) {
        int i = f >> 5, c = f & 31;
        *(float4*)(w_s + f) = *(const float4*)(g_Wc + i * 128 + cc * 32 + c);
    }
    __syncthreads();

    const int tx = tid & 31;
    const int ty = tid >> 5;

    float a0 = 0.f, a1 = 0.f;
#pragma unroll 8
    for (int i = 0; i < 128; i++) {
        float w = w_s[i * 32 + tx];
        a0 = fmaf(a_s[(2 * ty) * 128 + i],     w, a0);
        a1 = fmaf(a_s[(2 * ty + 1) * 128 + i], w, a1);
    }

    const int col = cc * 32 + tx;
    const float bias = g_bc[col];
    g_pre[(r0 + 2 * ty) * 128 + col]     = a0 + bias;
    g_pre[(r0 + 2 * ty + 1) * 128 + col] = a1 + bias;
}

// ======================================================================
// Kernel 4: RNN + regressor. grid 16 x 128 threads.
// One thread = one output column; full W_hh column in 64 packed f32x2
// registers; h broadcast from smem; NO cross-thread reduction; one
// barrier per step. pre prefetched two steps ahead.
// ======================================================================
__device__ __forceinline__ float fast_tanh(float z)
{
    float e2 = __expf(2.f * z);
    return 1.f - __fdividef(2.f, e2 + 1.f);
}

__device__ __forceinline__ void ffma2(ull& acc, ull a, ull b)
{
    asm("fma.rn.f32x2 %0, %1, %2, %0;" : "+l"(acc) : "l"(a), "l"(b));
}
__device__ __forceinline__ ull fadd2(ull a, ull b)
{
    ull r; asm("add.rn.f32x2 %0, %1, %2;" : "=l"(r) : "l"(a), "l"(b)); return r;
}
__device__ __forceinline__ float2 unpack2(ull a)
{
    float2 v; asm("mov.b64 {%0,%1}, %2;" : "=f"(v.x), "=f"(v.y) : "l"(a)); return v;
}

__global__ void __launch_bounds__(128, 1)
rnn_regr_kernel(const float* __restrict__ W_hh,
                const float* __restrict__ r1_w, const float* __restrict__ r1_b,
                const float* __restrict__ r2_w, const float* __restrict__ r2_b,
                const float* __restrict__ r3_w, const float* __restrict__ r3_b,
                const float* __restrict__ r4_w, const float* __restrict__ r4_b,
                float* __restrict__ out)
{
    __shared__ float h2[2][128];
    __shared__ float v_s[128];
    __shared__ float part[4][8];

    const int tid = threadIdx.x;        // output column j

    // Whole W_hh column in packed registers (coalesced loads across lanes)
    ull wreg[64];
#pragma unroll
    for (int k = 0; k < 64; k++) {
        union { float2 f; ull u; } p;
        p.f.x = W_hh[(2 * k) * 128 + tid];
        p.f.y = W_hh[(2 * k + 1) * 128 + tid];
        wreg[k] = p.u;
    }

    const float* pre_b = g_pre + blockIdx.x * LQ_ * ET_;

    // step 0 (h_prev = 0)
    h2[0][tid] = fast_tanh(pre_b[tid]);
    float pre1 = pre_b[128 + tid];
    float pre2 = pre_b[256 + tid];
    __syncthreads();

    int cb = 0;
    for (int step = 1; step < LQ_; step++) {
        float pre3 = (step + 2 < LQ_) ? pre_b[(step + 2) * 128 + tid] : 0.f;

        const ull* hp = (const ull*)h2[cb];
        ull a0 = 0, a1 = 0, a2 = 0, a3 = 0;
#pragma unroll
        for (int k = 0; k < 64; k += 4) {
            ffma2(a0, hp[k],     wreg[k]);
            ffma2(a1, hp[k + 1], wreg[k + 1]);
            ffma2(a2, hp[k + 2], wreg[k + 2]);
            ffma2(a3, hp[k + 3], wreg[k + 3]);
        }
        ull s01 = fadd2(fadd2(a0, a1), fadd2(a2, a3));
        float2 sv = unpack2(s01);
        float hn = fast_tanh(pre1 + sv.x + sv.y);
        h2[cb ^ 1][tid] = hn;
        cb ^= 1;
        pre1 = pre2;
        pre2 = pre3;
        __syncthreads();
    }

    // ---------------- regressor: 3 x (128->128), no activations ----------------
    // layer 1: v = h @ r1_w + r1_b
    {
        const float* hin = h2[cb];
        float acc = r1_b[tid];
#pragma unroll 8
        for (int i = 0; i < 128; i++)
            acc = fmaf(hin[i], r1_w[i * 128 + tid], acc);
        v_s[tid] = acc;
    }
    __syncthreads();
    {
        float acc = r2_b[tid];
#pragma unroll 8
        for (int i = 0; i < 128; i++)
            acc = fmaf(v_s[i], r2_w[i * 128 + tid], acc);
        h2[0][tid] = acc;
    }
    __syncthreads();
    {
        float acc = r3_b[tid];
#pragma unroll 8
        for (int i = 0; i < 128; i++)
            acc = fmaf(h2[0][i], r3_w[i * 128 + tid], acc);
        v_s[tid] = acc;
    }
    __syncthreads();

    // final 128 -> 8: warp-level partials, then combine
    {
        const int w = tid >> 5, lane = tid & 31;
        float vo = v_s[tid];
        float p[8];
#pragma unroll
        for (int o = 0; o < 8; o++)
            p[o] = vo * r4_w[tid * 8 + o];
#pragma unroll
        for (int off = 16; off; off >>= 1)
#pragma unroll
            for (int o = 0; o < 8; o++)
                p[o] += __shfl_xor_sync(0xffffffffu, p[o], off);
        if (lane < 8) part[w][lane] = p[lane];
    }
    __syncthreads();
    if (tid < 8)
        out[blockIdx.x * 8 + tid] = part[0][tid] + part[1][tid] +
                                    part[2][tid] + part[3][tid] + r4_b[tid];
}

// ======================================================================
extern "C" void kernel_launch(void* const* d_in, const int* in_sizes, int n_in,
                              void* d_out, int out_size)
{
    const float* x     = (const float*)d_in[0];
    const float* times = (const float*)d_in[1];
    const float* mask  = (const float*)d_in[2];
    const float* query = (const float*)d_in[3];
    const float* w_lin = (const float*)d_in[4];
    const float* b_lin = (const float*)d_in[5];
    const float* w_per = (const float*)d_in[6];
    const float* b_per = (const float*)d_in[7];
    const float* Wq    = (const float*)d_in[8];
    const float* bq    = (const float*)d_in[9];
    const float* Wk    = (const float*)d_in[10];
    const float* bk    = (const float*)d_in[11];
    const float* Wo    = (const float*)d_in[12];
    const float* bo    = (const float*)d_in[13];
    const float* W_ih  = (const float*)d_in[14];
    const float* b_ih  = (const float*)d_in[15];
    const float* W_hh  = (const float*)d_in[16];
    const float* b_hh  = (const float*)d_in[17];
    const float* r1_w  = (const float*)d_in[18];
    const float* r1_b  = (const float*)d_in[19];
    const float* r2_w  = (const float*)d_in[20];
    const float* r2_b  = (const float*)d_in[21];
    const float* r3_w  = (const float*)d_in[22];
    const float* r3_b  = (const float*)d_in[23];
    const float* r4_w  = (const float*)d_in[24];
    const float* r4_b  = (const float*)d_in[25];
    float* out = (float*)d_out;

    const int S1_SMEM = (16 * 128 + 128 * 128) * 4;  // 73728
    cudaFuncSetAttribute(stage1_kernel,
                         cudaFuncAttributeMaxDynamicSharedMemorySize, S1_SMEM);
    stage1_kernel<<<269, 256, S1_SMEM>>>(times, query, w_lin, b_lin, w_per, b_per,
                                         Wk, bk, Wq, bq, Wo, bo, W_ih, b_ih, b_hh);

    const int ATTN_SMEM = (512 + 4096) * 4 + 256 * 32 * 8;  // 83968
    cudaFuncSetAttribute(attn_kernel,
                         cudaFuncAttributeMaxDynamicSharedMemorySize, ATTN_SMEM);
    attn_kernel<<<dim3(4, 4, 16), 512, ATTN_SMEM>>>(x, mask);

    pre_kernel<<<dim3(4, 64), 256>>>();

    rnn_regr_kernel<<<16, 128>>>(W_hh, r1_w, r1_b, r2_w, r2_b,
                                 r3_w, r3_b, r4_w, r4_b, out);
}

// round 6
// speedup vs baseline: 1.0860x; 1.0834x over previous
#include <cuda_runtime.h>
#include <cuda_bf16.h>
#include <math.h>

// Problem constants
#define B_   16
#define L_   256
#define LQ_  64
#define ET_  128
#define H_   4
#define ETK_ 32
#define DIM_ 64
#define D_IN_ 32
#define IE_  8

typedef unsigned long long ull;

// ---------------- scratch (device globals; no allocation) ----------------
__device__ float g_q[H_ * LQ_ * ETK_];          // (h, q, e)  pre-scaled by 1/sqrt(32)
__device__ float g_k[B_ * H_ * L_ * ETK_];      // (b, h, l, e)
__device__ float g_att[B_ * LQ_ * ET_];         // (b, q, h*32+d)  compact (ones folded)
__device__ float g_Wc[ET_ * ET_];               // 128 x 128 : compact rows of Wo @ W_ih
__device__ float g_bc[ET_];                     // combined bias (incl. ones-rows fold)
__device__ float g_pre[B_ * LQ_ * ET_];         // (b, t, j)

// ======================================================================
// Kernel 1 (fused): time-embed + Q/K projections  AND  Wc/bc combine.
// ======================================================================
__global__ void stage1_kernel(
    const float* __restrict__ times, const float* __restrict__ query,
    const float* __restrict__ w_lin, const float* __restrict__ b_lin,
    const float* __restrict__ w_per, const float* __restrict__ b_per,
    const float* __restrict__ Wk, const float* __restrict__ bk,
    const float* __restrict__ Wq, const float* __restrict__ bq,
    const float* __restrict__ Wo, const float* __restrict__ bo,
    const float* __restrict__ W_ih, const float* __restrict__ b_ih,
    const float* __restrict__ b_hh)
{
    extern __shared__ float sm[];
    float* s_a = sm;              // 16 x 128
    float* s_w = sm + 16 * 128;   // 128 x 128
    __shared__ float tv[16];

    const int tid = threadIdx.x;
    const int bx  = blockIdx.x;
    const int tx = tid & 31;
    const int ty = tid >> 5;

    if (bx < 260) {
        const bool is_q = (bx >= 256);
        const int r0 = bx * 16;
        if (tid < 16) tv[tid] = is_q ? query[r0 - 4096 + tid] : times[r0 + tid];
        __syncthreads();

        const float wl = w_lin[0], bl = b_lin[0];
        for (int idx = tid; idx < 16 * 128; idx += 256) {
            int r = idx >> 7, c = idx & 127;
            float t = tv[r];
            s_a[idx] = (c == 0) ? fmaf(t, wl, bl)
                                : __sinf(fmaf(t, w_per[c - 1], b_per[c - 1]));
        }
        const float* W    = is_q ? Wq : Wk;
        const float* bias = is_q ? bq : bk;
#pragma unroll
        for (int idx = tid * 4; idx < 128 * 128; idx += 1024)
            *(float4*)(s_w + idx) = *(const float4*)(W + idx);
        __syncthreads();

        float acc[2][4];
#pragma unroll
        for (int r = 0; r < 2; r++)
#pragma unroll
            for (int c = 0; c < 4; c++) acc[r][c] = 0.f;

#pragma unroll 4
        for (int i = 0; i < 128; i++) {
            float4 w = *(const float4*)(s_w + i * 128 + 4 * tx);
            float e0 = s_a[(2 * ty) * 128 + i];
            float e1 = s_a[(2 * ty + 1) * 128 + i];
            acc[0][0] = fmaf(e0, w.x, acc[0][0]); acc[0][1] = fmaf(e0, w.y, acc[0][1]);
            acc[0][2] = fmaf(e0, w.z, acc[0][2]); acc[0][3] = fmaf(e0, w.w, acc[0][3]);
            acc[1][0] = fmaf(e1, w.x, acc[1][0]); acc[1][1] = fmaf(e1, w.y, acc[1][1]);
            acc[1][2] = fmaf(e1, w.z, acc[1][2]); acc[1][3] = fmaf(e1, w.w, acc[1][3]);
        }

        const float scale = is_q ? 0.17677669529663687f : 1.0f;
#pragma unroll
        for (int r = 0; r < 2; r++) {
            int grow = r0 + 2 * ty + r;
#pragma unroll
            for (int c = 0; c < 4; c++) {
                int col = 4 * tx + c;
                float v = (acc[r][c] + bias[col]) * scale;
                int h = col >> 5, e = col & 31;
                if (is_q) g_q[(h * LQ_ + (grow - 4096)) * ETK_ + e] = v;
                else {
                    int b = grow >> 8, l = grow & 255;
                    g_k[((b * H_ + h) * L_ + l) * ETK_ + e] = v;
                }
            }
        }
    } else if (bx < 268) {
        const int cr0 = (bx - 260) * 16;
        for (int idx = tid; idx < 16 * 128; idx += 256) {
            int rr = idx >> 7, c = idx & 127;
            int cr = cr0 + rr;
            int r = (cr >> 5) * 64 + (cr & 31);
            s_a[idx] = Wo[r * 128 + c];
        }
#pragma unroll
        for (int idx = tid * 4; idx < 128 * 128; idx += 1024)
            *(float4*)(s_w + idx) = *(const float4*)(W_ih + idx);
        __syncthreads();

        float acc[2][4];
#pragma unroll
        for (int r = 0; r < 2; r++)
#pragma unroll
            for (int c = 0; c < 4; c++) acc[r][c] = 0.f;

#pragma unroll 4
        for (int i = 0; i < 128; i++) {
            float4 w = *(const float4*)(s_w + i * 128 + 4 * tx);
            float e0 = s_a[(2 * ty) * 128 + i];
            float e1 = s_a[(2 * ty + 1) * 128 + i];
            acc[0][0] = fmaf(e0, w.x, acc[0][0]); acc[0][1] = fmaf(e0, w.y, acc[0][1]);
            acc[0][2] = fmaf(e0, w.z, acc[0][2]); acc[0][3] = fmaf(e0, w.w, acc[0][3]);
            acc[1][0] = fmaf(e1, w.x, acc[1][0]); acc[1][1] = fmaf(e1, w.y, acc[1][1]);
            acc[1][2] = fmaf(e1, w.z, acc[1][2]); acc[1][3] = fmaf(e1, w.w, acc[1][3]);
        }
#pragma unroll
        for (int r = 0; r < 2; r++)
#pragma unroll
            for (int c = 0; c < 4; c++)
                g_Wc[(cr0 + 2 * ty + r) * 128 + 4 * tx + c] = acc[r][c];
    } else {
        const int j = tid & 127, hf = tid >> 7;
        float accv = 0.f;
#pragma unroll 4
        for (int i = 0; i < 64; i++) {
            int oi = hf * 64 + i;
            int r = (oi >> 5) * 64 + 32 + (oi & 31);
            accv += Wo[r * 128 + j];
        }
        s_a[hf * 128 + j] = accv;
        __syncthreads();
        float v = 0.f;
        if (tid < 128) v = bo[tid] + s_a[tid] + s_a[128 + tid];
        __syncthreads();
        if (tid < 128) s_a[tid] = v;
#pragma unroll
        for (int idx = tid * 4; idx < 128 * 128; idx += 1024)
            *(float4*)(s_w + idx) = *(const float4*)(W_ih + idx);
        __syncthreads();
        if (tid < 128) {
            float acc = b_ih[tid] + b_hh[tid];
#pragma unroll 8
            for (int i = 0; i < 128; i++)
                acc = fmaf(s_a[i], s_w[i * 128 + tid], acc);
            g_bc[tid] = acc;
        }
    }
}

// ======================================================================
// Kernel 2: masked per-feature attention (compact output).
// ======================================================================
__global__ void attn_kernel(const float* __restrict__ x,
                            const float* __restrict__ mask)
{
    extern __shared__ float smem[];
    float*  qv  = smem;
    float*  s_s = smem + 512;
    float2* mxm = (float2*)(smem + 512 + 4096);

    const int tid = threadIdx.x;
    const int qt = blockIdx.x, h = blockIdx.y, b = blockIdx.z;

    qv[tid] = g_q[(h * LQ_ + qt * 16) * ETK_ + tid];

    const float* xb = x    + b * L_ * D_IN_;
    const float* mb = mask + b * L_ * D_IN_;
    for (int idx = tid; idx < L_ * D_IN_; idx += 512) {
        float m = mb[idx];
        mxm[idx] = make_float2(m * xb[idx], m);
    }
    __syncthreads();

    {
        const int k  = tid & 255;
        const int qh = tid >> 8;
        const float* kp = g_k + ((b * H_ + h) * L_ + k) * ETK_;
        float kv[32];
#pragma unroll
        for (int i = 0; i < 8; i++) {
            float4 v = *(const float4*)(kp + 4 * i);
            kv[4 * i] = v.x; kv[4 * i + 1] = v.y; kv[4 * i + 2] = v.z; kv[4 * i + 3] = v.w;
        }
#pragma unroll
        for (int qq = 0; qq < 8; qq++) {
            int q = qh * 8 + qq;
            float acc = 0.f;
#pragma unroll
            for (int e = 0; e < 32; e++) acc = fmaf(qv[q * 32 + e], kv[e], acc);
            s_s[q * 256 + k] = acc;
        }
    }
    __syncthreads();

    {
        const int wq = tid >> 5, lane = tid & 31;
        float vals[8], m = -1e30f;
#pragma unroll
        for (int i = 0; i < 8; i++) {
            vals[i] = s_s[wq * 256 + lane + 32 * i];
            m = fmaxf(m, vals[i]);
        }
#pragma unroll
        for (int off = 16; off; off >>= 1)
            m = fmaxf(m, __shfl_xor_sync(0xffffffffu, m, off));
#pragma unroll
        for (int i = 0; i < 8; i++)
            s_s[wq * 256 + lane + 32 * i] = __expf(vals[i] - m);
    }
    __syncthreads();

    {
        const int q = tid >> 5, d = tid & 31;
        float num = 0.f, den = 0.f;
        const float* ep = s_s + q * 256;
        const float2* vp = mxm + d;
#pragma unroll 4
        for (int k = 0; k < 256; k++) {
            float  e = ep[k];
            float2 v = vp[k * 32];
            num = fmaf(e, v.x, num);
            den = fmaf(e, v.y, den);
        }
        float att = (den > 0.f) ? (num / den) : 0.f;
        g_att[(b * LQ_ + qt * 16 + q) * ET_ + h * ETK_ + d] = att;
    }
}

// ======================================================================
// Kernel 3: pre = att_c @ Wc + bc   (1024 x 128, K=128)
// ======================================================================
__global__ void pre_kernel()
{
    __shared__ float a_s[16 * 128];
    __shared__ float w_s[128 * 32];

    const int tid = threadIdx.x;
    const int cc = blockIdx.x;
    const int r0 = blockIdx.y * 16;

#pragma unroll
    for (int idx = tid * 4; idx < 16 * 128; idx += 1024)
        *(float4*)(a_s + idx) = *(const float4*)(g_att + r0 * 128 + idx);

#pragma unroll
    for (int f = tid * 4; f < 128 * 32; f += 1024) {
        int i = f >> 5, c = f & 31;
        *(float4*)(w_s + f) = *(const float4*)(g_Wc + i * 128 + cc * 32 + c);
    }
    __syncthreads();

    const int tx = tid & 31;
    const int ty = tid >> 5;

    float a0 = 0.f, a1 = 0.f;
#pragma unroll 8
    for (int i = 0; i < 128; i++) {
        float w = w_s[i * 32 + tx];
        a0 = fmaf(a_s[(2 * ty) * 128 + i],     w, a0);
        a1 = fmaf(a_s[(2 * ty + 1) * 128 + i], w, a1);
    }

    const int col = cc * 32 + tx;
    const float bias = g_bc[col];
    g_pre[(r0 + 2 * ty) * 128 + col]     = a0 + bias;
    g_pre[(r0 + 2 * ty + 1) * 128 + col] = a1 + bias;
}

// ======================================================================
// Kernel 4: RNN + regressor. grid 16 x 128 threads.
// One thread = one output column; W_hh column in 64 packed f32x2 regs;
// ALL pre rows staged in smem up front (32KB) -> per-step loop touches
// ONLY smem/registers. One barrier per step.
// ======================================================================
__device__ __forceinline__ float fast_tanh(float z)
{
    float e2 = __expf(2.f * z);
    return 1.f - __fdividef(2.f, e2 + 1.f);
}

__device__ __forceinline__ void ffma2(ull& acc, ull a, ull b)
{
    asm("fma.rn.f32x2 %0, %1, %2, %0;" : "+l"(acc) : "l"(a), "l"(b));
}
__device__ __forceinline__ ull fadd2(ull a, ull b)
{
    ull r; asm("add.rn.f32x2 %0, %1, %2;" : "=l"(r) : "l"(a), "l"(b)); return r;
}
__device__ __forceinline__ float2 unpack2(ull a)
{
    float2 v; asm("mov.b64 {%0,%1}, %2;" : "=f"(v.x), "=f"(v.y) : "l"(a)); return v;
}

__global__ void __launch_bounds__(128, 1)
rnn_regr_kernel(const float* __restrict__ W_hh,
                const float* __restrict__ r1_w, const float* __restrict__ r1_b,
                const float* __restrict__ r2_w, const float* __restrict__ r2_b,
                const float* __restrict__ r3_w, const float* __restrict__ r3_b,
                const float* __restrict__ r4_w, const float* __restrict__ r4_b,
                float* __restrict__ out)
{
    __shared__ float pre_s[LQ_ * ET_];   // 32 KB: all steps' pre rows
    __shared__ float h2[2][128];
    __shared__ float v_s[128];
    __shared__ float part[4][8];

    const int tid = threadIdx.x;        // output column j

    // Stage entire pre slab for this batch into smem (coalesced float4)
    {
        const float4* src = (const float4*)(g_pre + blockIdx.x * LQ_ * ET_);
        float4* dst = (float4*)pre_s;
#pragma unroll
        for (int i = 0; i < 16; i++)
            dst[tid + 128 * i] = src[tid + 128 * i];
    }

    // Whole W_hh column in packed registers (coalesced loads across lanes)
    ull wreg[64];
#pragma unroll
    for (int k = 0; k < 64; k++) {
        union { float2 f; ull u; } p;
        p.f.x = W_hh[(2 * k) * 128 + tid];
        p.f.y = W_hh[(2 * k + 1) * 128 + tid];
        wreg[k] = p.u;
    }
    __syncthreads();

    // step 0 (h_prev = 0)
    h2[0][tid] = fast_tanh(pre_s[tid]);
    __syncthreads();

    int cb = 0;
#pragma unroll 1
    for (int step = 1; step < LQ_; step++) {
        const ull* hp = (const ull*)h2[cb];
        ull a0 = 0, a1 = 0, a2 = 0, a3 = 0;
#pragma unroll
        for (int k = 0; k < 64; k += 4) {
            ffma2(a0, hp[k],     wreg[k]);
            ffma2(a1, hp[k + 1], wreg[k + 1]);
            ffma2(a2, hp[k + 2], wreg[k + 2]);
            ffma2(a3, hp[k + 3], wreg[k + 3]);
        }
        ull s01 = fadd2(fadd2(a0, a1), fadd2(a2, a3));
        float2 sv = unpack2(s01);
        float hn = fast_tanh(pre_s[step * 128 + tid] + sv.x + sv.y);
        h2[cb ^ 1][tid] = hn;
        cb ^= 1;
        __syncthreads();
    }

    // ---------------- regressor: 3 x (128->128), no activations ----------------
    {
        const float* hin = h2[cb];
        float acc = r1_b[tid];
#pragma unroll 16
        for (int i = 0; i < 128; i++)
            acc = fmaf(hin[i], r1_w[i * 128 + tid], acc);
        v_s[tid] = acc;
    }
    __syncthreads();
    {
        float acc = r2_b[tid];
#pragma unroll 16
        for (int i = 0; i < 128; i++)
            acc = fmaf(v_s[i], r2_w[i * 128 + tid], acc);
        h2[0][tid] = acc;
    }
    __syncthreads();
    {
        float acc = r3_b[tid];
#pragma unroll 16
        for (int i = 0; i < 128; i++)
            acc = fmaf(h2[0][i], r3_w[i * 128 + tid], acc);
        v_s[tid] = acc;
    }
    __syncthreads();

    // final 128 -> 8
    {
        const int w = tid >> 5, lane = tid & 31;
        float vo = v_s[tid];
        float p[8];
#pragma unroll
        for (int o = 0; o < 8; o++)
            p[o] = vo * r4_w[tid * 8 + o];
#pragma unroll
        for (int off = 16; off; off >>= 1)
#pragma unroll
            for (int o = 0; o < 8; o++)
                p[o] += __shfl_xor_sync(0xffffffffu, p[o], off);
        if (lane < 8) part[w][lane] = p[lane];
    }
    __syncthreads();
    if (tid < 8)
        out[blockIdx.x * 8 + tid] = part[0][tid] + part[1][tid] +
                                    part[2][tid] + part[3][tid] + r4_b[tid];
}

// ======================================================================
extern "C" void kernel_launch(void* const* d_in, const int* in_sizes, int n_in,
                              void* d_out, int out_size)
{
    const float* x     = (const float*)d_in[0];
    const float* times = (const float*)d_in[1];
    const float* mask  = (const float*)d_in[2];
    const float* query = (const float*)d_in[3];
    const float* w_lin = (const float*)d_in[4];
    const float* b_lin = (const float*)d_in[5];
    const float* w_per = (const float*)d_in[6];
    const float* b_per = (const float*)d_in[7];
    const float* Wq    = (const float*)d_in[8];
    const float* bq    = (const float*)d_in[9];
    const float* Wk    = (const float*)d_in[10];
    const float* bk    = (const float*)d_in[11];
    const float* Wo    = (const float*)d_in[12];
    const float* bo    = (const float*)d_in[13];
    const float* W_ih  = (const float*)d_in[14];
    const float* b_ih  = (const float*)d_in[15];
    const float* W_hh  = (const float*)d_in[16];
    const float* b_hh  = (const float*)d_in[17];
    const float* r1_w  = (const float*)d_in[18];
    const float* r1_b  = (const float*)d_in[19];
    const float* r2_w  = (const float*)d_in[20];
    const float* r2_b  = (const float*)d_in[21];
    const float* r3_w  = (const float*)d_in[22];
    const float* r3_b  = (const float*)d_in[23];
    const float* r4_w  = (const float*)d_in[24];
    const float* r4_b  = (const float*)d_in[25];
    float* out = (float*)d_out;

    const int S1_SMEM = (16 * 128 + 128 * 128) * 4;  // 73728
    cudaFuncSetAttribute(stage1_kernel,
                         cudaFuncAttributeMaxDynamicSharedMemorySize, S1_SMEM);
    stage1_kernel<<<269, 256, S1_SMEM>>>(times, query, w_lin, b_lin, w_per, b_per,
                                         Wk, bk, Wq, bq, Wo, bo, W_ih, b_ih, b_hh);

    const int ATTN_SMEM = (512 + 4096) * 4 + 256 * 32 * 8;  // 83968
    cudaFuncSetAttribute(attn_kernel,
                         cudaFuncAttributeMaxDynamicSharedMemorySize, ATTN_SMEM);
    attn_kernel<<<dim3(4, 4, 16), 512, ATTN_SMEM>>>(x, mask);

    pre_kernel<<<dim3(4, 64), 256>>>();

    rnn_regr_kernel<<<16, 128>>>(W_hh, r1_w, r1_b, r2_w, r2_b,
                                 r3_w, r3_b, r4_w, r4_b, out);
}